// round 6
// baseline (speedup 1.0000x reference)
#include <cuda_runtime.h>
#include <cuda_fp16.h>
#include <cstdint>

// Problem constants
#define TOKENS 2048
#define HIDDEN 2048
#define INTER  5632
#define NEXP   8
#define TOPK   2
#define NPAIR  4096

#define BM 128
#define BN 128
#define BK 32
#define MAXMT 32        // worst-case m-tiles per expert

// smem geometry (bytes): A row = 32 halves (64B) padded to 80B;
// W row (k-major) = 128 halves (256B) padded to 272B. Both conflict-free for ldmatrix.
#define A_ROWB 80
#define W_ROWB 272
#define A_SZ   (128 * A_ROWB)      // 10240
#define W_SZ   (32 * W_ROWB)       // 8704
#define G1_BUF (A_SZ + 2 * W_SZ)   // 27648
#define G2_BUF (A_SZ + W_SZ)       // 18944
#define G1_SMEM (2 * G1_BUF)       // 55296 (dynamic)
#define G2_SMEM (2 * G2_BUF)       // 37888 (static)

// -------- persistent device scratch --------
__device__ int      d_cnt[NEXP];
__device__ int      d_off[NEXP];
__device__ int      d_tok[NPAIR];
__device__ int      d_pos[NPAIR];
__device__ uint32_t d_hbuf[(size_t)(NPAIR + BM) * (INTER / 2)];  // fp16 pairs, padded rows
__device__ float    d_ybuf[(size_t)NPAIR * HIDDEN];

// ---------------------------------------------------------------------------
// helpers
// ---------------------------------------------------------------------------
__device__ __forceinline__ uint32_t packh2(float lo, float hi) {
    __half2 h = __floats2half2_rn(lo, hi);
    return *reinterpret_cast<uint32_t*>(&h);
}
__device__ __forceinline__ uint32_t smem_u32(const void* p) {
    uint32_t a;
    asm("{ .reg .u64 t; cvta.to.shared.u64 t, %1; cvt.u32.u64 %0, t; }" : "=r"(a) : "l"(p));
    return a;
}
__device__ __forceinline__ void mma16816(float c[4], const uint32_t a[4],
                                         uint32_t b0, uint32_t b1) {
    asm volatile(
        "mma.sync.aligned.m16n8k16.row.col.f32.f16.f16.f32 "
        "{%0,%1,%2,%3}, {%4,%5,%6,%7}, {%8,%9}, {%0,%1,%2,%3};\n"
        : "+f"(c[0]), "+f"(c[1]), "+f"(c[2]), "+f"(c[3])
        : "r"(a[0]), "r"(a[1]), "r"(a[2]), "r"(a[3]), "r"(b0), "r"(b1));
}
#define LDSM_X4(r, a)                                                            \
    asm volatile("ldmatrix.sync.aligned.m8n8.x4.shared.b16 {%0,%1,%2,%3}, [%4];" \
        : "=r"((r)[0]), "=r"((r)[1]), "=r"((r)[2]), "=r"((r)[3]) : "r"(a))
#define LDSM_X4T(r, a)                                                                 \
    asm volatile("ldmatrix.sync.aligned.m8n8.x4.trans.shared.b16 {%0,%1,%2,%3}, [%4];" \
        : "=r"((r)[0]), "=r"((r)[1]), "=r"((r)[2]), "=r"((r)[3]) : "r"(a))
#define STS128(a, q0, q1, q2, q3)                                                \
    asm volatile("st.shared.v4.b32 [%0], {%1,%2,%3,%4};"                         \
        :: "r"(a), "r"(q0), "r"(q1), "r"(q2), "r"(q3) : "memory")

// ---------------------------------------------------------------------------
// Routing: bucket 4096 (token,k) pairs by expert; inverse permutation d_pos.
// ---------------------------------------------------------------------------
__global__ void route_kernel(const int* __restrict__ eidx) {
    __shared__ int s_cnt[NEXP], s_off[NEXP], s_cur[NEXP];
    int t = threadIdx.x;
    if (t < NEXP) s_cnt[t] = 0;
    __syncthreads();
    for (int p = t; p < NPAIR; p += blockDim.x) atomicAdd(&s_cnt[eidx[p]], 1);
    __syncthreads();
    if (t == 0) {
        int o = 0;
        for (int e = 0; e < NEXP; e++) { s_off[e] = o; s_cur[e] = o; o += s_cnt[e]; }
    }
    __syncthreads();
    for (int p = t; p < NPAIR; p += blockDim.x) {
        int pos = atomicAdd(&s_cur[eidx[p]], 1);
        d_tok[pos] = p >> 1;
        d_pos[p]   = pos;
    }
    if (t < NEXP) { d_cnt[t] = s_cnt[t]; d_off[t] = s_off[t]; }
}

// ---------------------------------------------------------------------------
// GEMM1: gate = Xg@W1, up = Xg@W3, h = silu(gate)*up -> d_hbuf (fp16 packed)
// 512 thr / 16 warps, warp tile 32x32, ldmatrix frags, double-buffered smem.
// ---------------------------------------------------------------------------
__global__ __launch_bounds__(512, 1)
void gemm1_kernel(const float* __restrict__ x,
                  const float* __restrict__ w1g,
                  const float* __restrict__ w3g) {
    const int e   = blockIdx.x >> 5;
    const int cnt = d_cnt[e];
    const int m0  = (blockIdx.x & 31) * BM;
    if (m0 >= cnt) return;
    const int n0  = blockIdx.y * BN;
    const int off = d_off[e];

    extern __shared__ char smem[];
    const uint32_t sb = smem_u32(smem);
    const int tid = threadIdx.x, wid = tid >> 5, lid = tid & 31;
    const int mg = wid >> 2, ng = wid & 3;          // 4x4 warp grid
    const int g  = lid >> 2, tg = lid & 3;

    // ---- fill tasks ----
    const int am = tid >> 2, ap = tid & 3;          // A: row, 16B part
    const int tok = (m0 + am < cnt) ? d_tok[off + m0 + am] : d_tok[off];
    const float* xA = x + (size_t)tok * HIDDEN + ap * 8;
    const uint32_t a_sts = am * A_ROWB + ap * 16;

    const int wk = tid >> 4, wn = tid & 15;         // W: k-row, 16B n-part
    const float* w1p = w1g + (size_t)e * HIDDEN * INTER + n0 + wn * 8;
    const float* w3p = w3g + (size_t)e * HIDDEN * INTER + n0 + wn * 8;
    const uint32_t w_sts = wk * W_ROWB + wn * 16;

    // ---- ldmatrix lane offsets ----
    const uint32_t a_off0 = (mg * 32 + (lid & 15)) * A_ROWB + (lid >> 4) * 16;
    const uint32_t a_off1 = a_off0 + 16 * A_ROWB;
    const uint32_t b_off0 = (((lid >> 3) & 1) * 8 + (lid & 7)) * W_ROWB
                          + ng * 64 + (lid >> 4) * 16;
    const uint32_t b_off1 = b_off0 + 32;

    float gacc[2][4][4], uacc[2][4][4];
#pragma unroll
    for (int mi = 0; mi < 2; mi++)
#pragma unroll
        for (int ni = 0; ni < 4; ni++)
#pragma unroll
            for (int r = 0; r < 4; r++) { gacc[mi][ni][r] = 0.f; uacc[mi][ni][r] = 0.f; }

    uint32_t apf[4], w1pf[4], w3pf[4];
    auto loadregs = [&](int k0) {
        float4 v0 = *(const float4*)(xA + k0);
        float4 v1 = *(const float4*)(xA + k0 + 4);
        apf[0] = packh2(v0.x, v0.y); apf[1] = packh2(v0.z, v0.w);
        apf[2] = packh2(v1.x, v1.y); apf[3] = packh2(v1.z, v1.w);
        const float* r1 = w1p + (size_t)(k0 + wk) * INTER;
        float4 u0 = *(const float4*)(r1);
        float4 u1 = *(const float4*)(r1 + 4);
        w1pf[0] = packh2(u0.x, u0.y); w1pf[1] = packh2(u0.z, u0.w);
        w1pf[2] = packh2(u1.x, u1.y); w1pf[3] = packh2(u1.z, u1.w);
        const float* r3 = w3p + (size_t)(k0 + wk) * INTER;
        float4 q0 = *(const float4*)(r3);
        float4 q1 = *(const float4*)(r3 + 4);
        w3pf[0] = packh2(q0.x, q0.y); w3pf[1] = packh2(q0.z, q0.w);
        w3pf[2] = packh2(q1.x, q1.y); w3pf[3] = packh2(q1.z, q1.w);
    };
    auto sts = [&](int buf) {
        const uint32_t base = sb + buf * G1_BUF;
        STS128(base + a_sts, apf[0], apf[1], apf[2], apf[3]);
        STS128(base + A_SZ + w_sts, w1pf[0], w1pf[1], w1pf[2], w1pf[3]);
        STS128(base + A_SZ + W_SZ + w_sts, w3pf[0], w3pf[1], w3pf[2], w3pf[3]);
    };

    loadregs(0); sts(0);
    __syncthreads();

    const int NC = HIDDEN / BK;   // 64
    for (int c = 0; c < NC; c++) {
        if (c + 1 < NC) loadregs((c + 1) * BK);
        const int buf = c & 1;
        const uint32_t Ab = sb + buf * G1_BUF;
        const uint32_t W1b = Ab + A_SZ, W3b = W1b + W_SZ;
#pragma unroll
        for (int kk = 0; kk < 2; kk++) {
            uint32_t af0[4], af1[4], b1f[8], b3f[8];
            LDSM_X4(af0, Ab + a_off0 + kk * 32);
            LDSM_X4(af1, Ab + a_off1 + kk * 32);
            LDSM_X4T(b1f,     W1b + b_off0 + kk * (16 * W_ROWB));
            LDSM_X4T(b1f + 4, W1b + b_off1 + kk * (16 * W_ROWB));
            LDSM_X4T(b3f,     W3b + b_off0 + kk * (16 * W_ROWB));
            LDSM_X4T(b3f + 4, W3b + b_off1 + kk * (16 * W_ROWB));
#pragma unroll
            for (int ni = 0; ni < 4; ni++) {
                mma16816(gacc[0][ni], af0, b1f[2 * ni], b1f[2 * ni + 1]);
                mma16816(gacc[1][ni], af1, b1f[2 * ni], b1f[2 * ni + 1]);
                mma16816(uacc[0][ni], af0, b3f[2 * ni], b3f[2 * ni + 1]);
                mma16816(uacc[1][ni], af1, b3f[2 * ni], b3f[2 * ni + 1]);
            }
        }
        if (c + 1 < NC) sts(buf ^ 1);
        __syncthreads();
    }

    // ---- epilogue: silu(gate)*up -> packed fp16 ----
#pragma unroll
    for (int mi = 0; mi < 2; mi++) {
#pragma unroll
        for (int ni = 0; ni < 4; ni++) {
            int r0 = m0 + mg * 32 + mi * 16 + g;
            int r1 = r0 + 8;
            int cw = n0 / 2 + ng * 16 + ni * 4 + tg;
            if (r0 < cnt) {
                float g0 = gacc[mi][ni][0], g1 = gacc[mi][ni][1];
                float h0 = g0 / (1.f + __expf(-g0)) * uacc[mi][ni][0];
                float h1 = g1 / (1.f + __expf(-g1)) * uacc[mi][ni][1];
                d_hbuf[(size_t)(off + r0) * (INTER / 2) + cw] = packh2(h0, h1);
            }
            if (r1 < cnt) {
                float g2 = gacc[mi][ni][2], g3 = gacc[mi][ni][3];
                float h2 = g2 / (1.f + __expf(-g2)) * uacc[mi][ni][2];
                float h3 = g3 / (1.f + __expf(-g3)) * uacc[mi][ni][3];
                d_hbuf[(size_t)(off + r1) * (INTER / 2) + cw] = packh2(h2, h3);
            }
        }
    }
}

// ---------------------------------------------------------------------------
// GEMM2: y = h @ W2 -> d_ybuf
// ---------------------------------------------------------------------------
__global__ __launch_bounds__(512, 1)
void gemm2_kernel(const float* __restrict__ w2g) {
    const int e   = blockIdx.x >> 5;
    const int cnt = d_cnt[e];
    const int m0  = (blockIdx.x & 31) * BM;
    if (m0 >= cnt) return;
    const int n0  = blockIdx.y * BN;
    const int off = d_off[e];

    __shared__ __align__(16) char smem2[G2_SMEM];
    const uint32_t sb = smem_u32(smem2);
    const int tid = threadIdx.x, wid = tid >> 5, lid = tid & 31;
    const int mg = wid >> 2, ng = wid & 3;
    const int g  = lid >> 2, tg = lid & 3;

    // A fill: packed fp16 straight from d_hbuf (padded rows -> always safe)
    const int am = tid >> 2, ap = tid & 3;
    const uint32_t* hA = d_hbuf + (size_t)(off + m0 + am) * (INTER / 2) + ap * 4;
    const uint32_t a_sts = am * A_ROWB + ap * 16;

    const int wk = tid >> 4, wn = tid & 15;
    const float* w2p = w2g + (size_t)e * INTER * HIDDEN + n0 + wn * 8;
    const uint32_t w_sts = wk * W_ROWB + wn * 16;

    const uint32_t a_off0 = (mg * 32 + (lid & 15)) * A_ROWB + (lid >> 4) * 16;
    const uint32_t a_off1 = a_off0 + 16 * A_ROWB;
    const uint32_t b_off0 = (((lid >> 3) & 1) * 8 + (lid & 7)) * W_ROWB
                          + ng * 64 + (lid >> 4) * 16;
    const uint32_t b_off1 = b_off0 + 32;

    float acc[2][4][4];
#pragma unroll
    for (int mi = 0; mi < 2; mi++)
#pragma unroll
        for (int ni = 0; ni < 4; ni++)
#pragma unroll
            for (int r = 0; r < 4; r++) acc[mi][ni][r] = 0.f;

    uint32_t apf[4], wpf[4];
    auto loadregs = [&](int c) {
        uint4 v = *(const uint4*)(hA + c * 16);     // 16 halves along k
        apf[0] = v.x; apf[1] = v.y; apf[2] = v.z; apf[3] = v.w;
        const float* r2 = w2p + (size_t)(c * BK + wk) * HIDDEN;
        float4 u0 = *(const float4*)(r2);
        float4 u1 = *(const float4*)(r2 + 4);
        wpf[0] = packh2(u0.x, u0.y); wpf[1] = packh2(u0.z, u0.w);
        wpf[2] = packh2(u1.x, u1.y); wpf[3] = packh2(u1.z, u1.w);
    };
    auto sts = [&](int buf) {
        const uint32_t base = sb + buf * G2_BUF;
        STS128(base + a_sts, apf[0], apf[1], apf[2], apf[3]);
        STS128(base + A_SZ + w_sts, wpf[0], wpf[1], wpf[2], wpf[3]);
    };

    loadregs(0); sts(0);
    __syncthreads();

    const int NC = INTER / BK;   // 176
    for (int c = 0; c < NC; c++) {
        if (c + 1 < NC) loadregs(c + 1);
        const int buf = c & 1;
        const uint32_t Ab = sb + buf * G2_BUF;
        const uint32_t Wb = Ab + A_SZ;
#pragma unroll
        for (int kk = 0; kk < 2; kk++) {
            uint32_t af0[4], af1[4], bf[8];
            LDSM_X4(af0, Ab + a_off0 + kk * 32);
            LDSM_X4(af1, Ab + a_off1 + kk * 32);
            LDSM_X4T(bf,     Wb + b_off0 + kk * (16 * W_ROWB));
            LDSM_X4T(bf + 4, Wb + b_off1 + kk * (16 * W_ROWB));
#pragma unroll
            for (int ni = 0; ni < 4; ni++) {
                mma16816(acc[0][ni], af0, bf[2 * ni], bf[2 * ni + 1]);
                mma16816(acc[1][ni], af1, bf[2 * ni], bf[2 * ni + 1]);
            }
        }
        if (c + 1 < NC) sts(buf ^ 1);
        __syncthreads();
    }

#pragma unroll
    for (int mi = 0; mi < 2; mi++) {
#pragma unroll
        for (int ni = 0; ni < 4; ni++) {
            int r0 = m0 + mg * 32 + mi * 16 + g;
            int r1 = r0 + 8;
            int col = n0 + ng * 32 + ni * 8 + tg * 2;
            if (r0 < cnt)
                *(float2*)(d_ybuf + (size_t)(off + r0) * HIDDEN + col) =
                    make_float2(acc[mi][ni][0], acc[mi][ni][1]);
            if (r1 < cnt)
                *(float2*)(d_ybuf + (size_t)(off + r1) * HIDDEN + col) =
                    make_float2(acc[mi][ni][2], acc[mi][ni][3]);
        }
    }
}

// ---------------------------------------------------------------------------
// Combine: out[t] = ew[2t]*y[pos[2t]] + ew[2t+1]*y[pos[2t+1]]
// ---------------------------------------------------------------------------
__global__ __launch_bounds__(256)
void combine_kernel(const float* __restrict__ ew, float* __restrict__ out) {
    const int t = blockIdx.x;
    const int p0 = d_pos[2 * t], p1 = d_pos[2 * t + 1];
    const float w0 = ew[2 * t], w1 = ew[2 * t + 1];
    const float4* y0 = (const float4*)(d_ybuf + (size_t)p0 * HIDDEN);
    const float4* y1 = (const float4*)(d_ybuf + (size_t)p1 * HIDDEN);
    float4* o = (float4*)(out + (size_t)t * HIDDEN);
#pragma unroll
    for (int i = threadIdx.x; i < HIDDEN / 4; i += 256) {
        float4 a = y0[i], b = y1[i], r;
        r.x = w0 * a.x + w1 * b.x; r.y = w0 * a.y + w1 * b.y;
        r.z = w0 * a.z + w1 * b.z; r.w = w0 * a.w + w1 * b.w;
        o[i] = r;
    }
}

// ---------------------------------------------------------------------------
// launch — inputs: x, expert_weights, w1, w2, w3, expert_indices
// ---------------------------------------------------------------------------
extern "C" void kernel_launch(void* const* d_in, const int* in_sizes, int n_in,
                              void* d_out, int out_size) {
    const float* x  = (const float*)d_in[0];
    const float* ew = (const float*)d_in[1];
    const float* w1 = (const float*)d_in[2];
    const float* w2 = (const float*)d_in[3];
    const float* w3 = (const float*)d_in[4];
    const int*   ei = (const int*)d_in[5];
    float* out = (float*)d_out;

    cudaFuncSetAttribute(gemm1_kernel, cudaFuncAttributeMaxDynamicSharedMemorySize, G1_SMEM);

    route_kernel<<<1, 256>>>(ei);

    dim3 g1(NEXP * MAXMT, INTER / BN);   // 256 x 44
    gemm1_kernel<<<g1, 512, G1_SMEM>>>(x, w1, w3);

    dim3 g2(NEXP * MAXMT, HIDDEN / BN);  // 256 x 16
    gemm2_kernel<<<g2, 512>>>(w2);

    combine_kernel<<<TOKENS, 256>>>(ew, out);
}